// round 5
// baseline (speedup 1.0000x reference)
#include <cuda_runtime.h>
#include <cuda_bf16.h>
#include <math.h>

#define N_NODES 50000
#define F_IN 128
#define F_OUT 64
#define E_MAX 1664000
#define SCAN_T 1024
#define GATHER_BLOCKS ((N_NODES + 7) / 8)   // 6250: one warp per node, 8 warps/block

// Scratch (allocation-free rule: __device__ globals)
__device__ float  g_h[N_NODES * F_OUT];   // x @ W
__device__ float  g_deg[N_NODES];
__device__ float  g_dinv[N_NODES];
__device__ int    g_cnt[N_NODES];
__device__ int    g_cur[N_NODES];
__device__ int    g_start[N_NODES + 1];
__device__ int    g_esrc[E_MAX];          // bucketed src per edge
__device__ float  g_ec[E_MAX];            // bucketed coefficient per edge
__device__ float  g_part[GATHER_BLOCKS];  // per-block logit partials
__device__ int    g_mode;                 // 0:A i64  1:A i32  2:B i64  3:B i32

// ---------------------------------------------------------------------------
// edge fetch helper: mode-selected pointer + dtype, clamped indices
// ---------------------------------------------------------------------------
__device__ __forceinline__ void edge_sd(const void* A, const void* B,
                                        int e, int E, int& src, int& dst) {
    int m = g_mode;
    const void* p = (m < 2) ? A : B;
    if ((m & 1) == 0) {
        const long long* el = (const long long*)p;
        src = (int)el[e];
        dst = (int)el[(size_t)E + e];
    } else {
        const int* el = (const int*)p;
        src = el[e];
        dst = el[E + e];
    }
    src = min(max(src, 0), N_NODES - 1);
    dst = min(max(dst, 0), N_NODES - 1);
}

// ---------------------------------------------------------------------------
// K0: detect edge_list dtype (and array identity) on device
// ---------------------------------------------------------------------------
__device__ __forceinline__ bool valid64(const void* p) {
    const long long* q = (const long long*)p;
    for (int i = 0; i < 64; i++) {
        long long v = q[i];
        if (v < 0 || v >= N_NODES) return false;
    }
    return true;
}
__device__ __forceinline__ bool valid32(const void* p) {
    const int* q = (const int*)p;
    for (int i = 0; i < 128; i++) {
        int v = q[i];
        if (v < 0 || v >= N_NODES) return false;
    }
    return true;
}
__global__ void k_detect(const void* A, const void* B) {
    if (valid64(A))      g_mode = 0;
    else if (valid32(A)) g_mode = 1;
    else if (valid64(B)) g_mode = 2;
    else                 g_mode = 3;
}

// ---------------------------------------------------------------------------
// K1: init counters + self-loop degree
// ---------------------------------------------------------------------------
__global__ void k_init() {
    int i = blockIdx.x * blockDim.x + threadIdx.x;
    if (i < N_NODES) { g_deg[i] = 1.0f; g_cnt[i] = 0; g_cur[i] = 0; }
}

// ---------------------------------------------------------------------------
// K2: h = x @ W   (x: [N,128] row-major, W: [128,64])
// ---------------------------------------------------------------------------
__global__ void k_gemm(const float* __restrict__ x, const float* __restrict__ W) {
    __shared__ float sW[F_IN * F_OUT];   // 32 KB
    __shared__ float sX[32 * F_IN];      // 16 KB

    int row0 = blockIdx.x * 32;

    const float4* W4  = (const float4*)W;
    float4*       sW4 = (float4*)sW;
    #pragma unroll
    for (int i = threadIdx.x; i < (F_IN * F_OUT) / 4; i += 256) sW4[i] = W4[i];

    int nrows = N_NODES - row0; if (nrows > 32) nrows = 32;
    const float4* X4  = (const float4*)(x + (size_t)row0 * F_IN);
    float4*       sX4 = (float4*)sX;
    for (int i = threadIdx.x; i < nrows * (F_IN / 4); i += 256) sX4[i] = X4[i];

    __syncthreads();

    int row = threadIdx.x >> 3;
    int cg  = threadIdx.x & 7;
    if (row0 + row >= N_NODES) return;

    float acc[8];
    #pragma unroll
    for (int j = 0; j < 8; j++) acc[j] = 0.f;

    const float* xr = &sX[row * F_IN];
    #pragma unroll 4
    for (int k = 0; k < F_IN; k++) {
        float xv = xr[k];
        const float* wr = &sW[k * F_OUT + cg * 8];
        #pragma unroll
        for (int j = 0; j < 8; j++) acc[j] = fmaf(xv, wr[j], acc[j]);
    }

    float* hp = g_h + (size_t)(row0 + row) * F_OUT + cg * 8;
    #pragma unroll
    for (int j = 0; j < 8; j++) hp[j] = acc[j];
}

// ---------------------------------------------------------------------------
// K3: histogram over dst + weighted degree (int + f32 atomics)
// ---------------------------------------------------------------------------
__global__ void k_hist(const void* elA, const void* elB,
                       const float* __restrict__ ew, int E) {
    int e = blockIdx.x * blockDim.x + threadIdx.x;
    if (e >= E) return;
    int src, dst;
    edge_sd(elA, elB, e, E, src, dst);
    atomicAdd(&g_cnt[dst], 1);
    atomicAdd(&g_deg[dst], ew[e]);
}

// ---------------------------------------------------------------------------
// K4: exclusive prefix scan of g_cnt -> g_start (single block)
// ---------------------------------------------------------------------------
__global__ void k_scan() {
    __shared__ int part[SCAN_T];
    const int chunk = (N_NODES + SCAN_T - 1) / SCAN_T;  // 49
    int tid = threadIdx.x;
    int base = tid * chunk;

    int s = 0;
    for (int j = 0; j < chunk; j++) {
        int idx = base + j;
        if (idx < N_NODES) s += g_cnt[idx];
    }
    part[tid] = s;
    __syncthreads();

    for (int off = 1; off < SCAN_T; off <<= 1) {
        int v = (tid >= off) ? part[tid - off] : 0;
        __syncthreads();
        part[tid] += v;
        __syncthreads();
    }

    int run = (tid > 0) ? part[tid - 1] : 0;
    for (int j = 0; j < chunk; j++) {
        int idx = base + j;
        if (idx < N_NODES) { g_start[idx] = run; run += g_cnt[idx]; }
    }
    if (tid == SCAN_T - 1) g_start[N_NODES] = run;
}

// ---------------------------------------------------------------------------
// K5: dinv = rsqrt(deg)
// ---------------------------------------------------------------------------
__global__ void k_dinv() {
    int i = blockIdx.x * blockDim.x + threadIdx.x;
    if (i >= N_NODES) return;
    g_dinv[i] = rsqrtf(g_deg[i]);   // deg >= 1 (self-loop)
}

// ---------------------------------------------------------------------------
// K6: bucket edges by dst, precomputing coefficient
// ---------------------------------------------------------------------------
__global__ void k_bucket(const void* elA, const void* elB,
                         const float* __restrict__ ew, int E) {
    int e = blockIdx.x * blockDim.x + threadIdx.x;
    if (e >= E) return;
    int src, dst;
    edge_sd(elA, elB, e, E, src, dst);
    float c = g_dinv[src] * ew[e] * g_dinv[dst];
    int pos = g_start[dst] + atomicAdd(&g_cur[dst], 1);
    g_esrc[pos] = src;
    g_ec[pos]   = c;
}

// ---------------------------------------------------------------------------
// K7: gather-aggregate (one warp per dst node) fused with relu(acc+b)·fc_w
// ---------------------------------------------------------------------------
__global__ void k_gather(const float* __restrict__ b,
                         const void* fwA, const void* fwB) {
    int gwarp = (blockIdx.x * blockDim.x + threadIdx.x) >> 5;
    int lane  = threadIdx.x & 31;
    int wid   = threadIdx.x >> 5;

    // fc_w is whichever 3.2M array is NOT the edge list
    const float* fcw = (g_mode < 2) ? (const float*)fwB : (const float*)fwA;

    float psum = 0.f;
    if (gwarp < N_NODES) {
        int n   = gwarp;
        int beg = g_start[n];
        int end = g_start[n + 1];

        float dv = g_dinv[n];
        float dd = dv * dv;                       // self-loop coefficient
        const float* hn = g_h + (size_t)n * F_OUT;
        float a0 = dd * hn[lane];
        float a1 = dd * hn[lane + 32];

        int i = beg;
        for (; i + 1 < end; i += 2) {
            int   s0 = g_esrc[i];     float c0 = g_ec[i];
            int   s1 = g_esrc[i + 1]; float c1 = g_ec[i + 1];
            const float* h0 = g_h + (size_t)s0 * F_OUT;
            const float* h1 = g_h + (size_t)s1 * F_OUT;
            float v00 = h0[lane], v01 = h0[lane + 32];
            float v10 = h1[lane], v11 = h1[lane + 32];
            a0 = fmaf(c0, v00, a0); a1 = fmaf(c0, v01, a1);
            a0 = fmaf(c1, v10, a0); a1 = fmaf(c1, v11, a1);
        }
        if (i < end) {
            int s0 = g_esrc[i]; float c0 = g_ec[i];
            const float* h0 = g_h + (size_t)s0 * F_OUT;
            a0 = fmaf(c0, h0[lane], a0);
            a1 = fmaf(c0, h0[lane + 32], a1);
        }

        a0 = fmaxf(a0 + b[lane], 0.f);
        a1 = fmaxf(a1 + b[lane + 32], 0.f);
        const float* fw = fcw + (size_t)n * F_OUT;
        psum = fmaf(a0, fw[lane], a1 * fw[lane + 32]);
    }

    #pragma unroll
    for (int o = 16; o; o >>= 1) psum += __shfl_down_sync(0xffffffffu, psum, o);

    __shared__ float ws[8];
    if (lane == 0) ws[wid] = psum;
    __syncthreads();
    if (threadIdx.x == 0) {
        float t = 0.f;
        #pragma unroll
        for (int k = 0; k < 8; k++) t += ws[k];
        g_part[blockIdx.x] = t;       // plain store — no atomics
    }
}

// ---------------------------------------------------------------------------
// K8: reduce per-block partials (double, non-atomic) + sigmoid
// ---------------------------------------------------------------------------
__global__ void k_final(const float* __restrict__ fcb, float* __restrict__ out) {
    __shared__ double sd[256];
    double s = 0.0;
    for (int i = threadIdx.x; i < GATHER_BLOCKS; i += 256) s += (double)g_part[i];
    sd[threadIdx.x] = s;
    __syncthreads();
    for (int off = 128; off; off >>= 1) {
        if (threadIdx.x < off) sd[threadIdx.x] += sd[threadIdx.x + off];
        __syncthreads();
    }
    if (threadIdx.x == 0) {
        double logit = sd[0] + (double)fcb[0];
        out[0] = (float)(1.0 / (1.0 + exp(-logit)));
    }
}

// ---------------------------------------------------------------------------
extern "C" void kernel_launch(void* const* d_in, const int* in_sizes, int n_in,
                              void* d_out, int out_size) {
    const float* x   = (const float*)d_in[0];   // [N,128]
    const void*  elA = d_in[1];                 // edge_list candidate (3.2M elems)
    const float* ea  = (const float*)d_in[2];   // [E]
    const float* W   = (const float*)d_in[3];   // [128,64]
    const float* b   = (const float*)d_in[4];   // [64]
    const void*  elB = d_in[5];                 // fc_w / swapped candidate (3.2M)
    const float* fcb = (const float*)d_in[6];   // [1]
    float*       out = (float*)d_out;

    const int E = in_sizes[2];                  // edge_attr element count

    k_detect<<<1, 1>>>(elA, elB);
    k_init<<<(N_NODES + 255) / 256, 256>>>();
    k_gemm<<<(N_NODES + 31) / 32, 256>>>(x, W);
    k_hist<<<(E + 255) / 256, 256>>>(elA, elB, ea, E);
    k_scan<<<1, SCAN_T>>>();
    k_dinv<<<(N_NODES + 255) / 256, 256>>>();
    k_bucket<<<(E + 255) / 256, 256>>>(elA, elB, ea, E);
    k_gather<<<GATHER_BLOCKS, 256>>>(b, elA, elB);
    k_final<<<1, 256>>>(fcb, out);
}